// round 15
// baseline (speedup 1.0000x reference)
#include <cuda_runtime.h>
#include <cuda_fp16.h>

#define N_NODES 100000
#define N_EDGES 1000000
#define N_GRAPHS 2048
#define SCAN_BS 512
#define SCAN_NB ((N_NODES + SCAN_BS - 1) / SCAN_BS)
#define HISTB ((N_EDGES + 1023) / 1024)
#define PADN (N_NODES + 128)
// k_mmtc smem: A tile 128 x 136 halves, B tile 128 x 72 halves
#define SA_H 136
#define SB_H 72
#define SMEM_MM (128 * SA_H * 2 + 128 * SB_H * 2)

typedef unsigned long long u64;
typedef unsigned char u8;

// ---------------- device scratch (no allocs allowed) ----------------
__device__ float  g_hA[N_NODES * 64];
__device__ __half g_hBh[PADN * 64];       // conv1 output, fp16 (padded rows)
__device__ __half g_meanH[PADN * 64];     // conv2 mean, fp16 (padded rows)
__device__ __half g_EpH[128 * 64];        // emb @ W1l, fp16 (16 KB, L1-resident)
__device__ float  g_Rp[128 * 64];         // emb @ W1r, fp32
__device__ __half g_W2h[128 * 64];        // rows 0-63 = W2r, 64-127 = W2l (fp16)
__device__ int    g_deg[N_NODES];         // INVARIANT: zero at kernel_launch entry
__device__ int    g_rowptr[N_NODES + 1];
__device__ int    g_cursor[N_NODES];
__device__ __align__(16) int g_colsrc[N_EDGES + 4];   // src node id per CSR slot
__device__ __align__(4)  u8  g_colvid[N_EDGES + 4];   // vocab id per CSR slot
__device__ int    g_gstart[N_GRAPHS + 1]; // graph -> first node index (batch sorted)
__device__ u64    g_lb[SCAN_NB];

// ---------------- helpers ----------------
__device__ __forceinline__ void hadd2(unsigned &d, unsigned a) {
    asm("add.rn.f16x2 %0, %0, %1;" : "+r"(d) : "r"(a));
}
__device__ __forceinline__ float2 h2f(unsigned h) {
    __half2 v = *reinterpret_cast<__half2*>(&h);
    return __half22float2(v);
}
__device__ __forceinline__ unsigned smem_u32(const void* p) {
    unsigned a;
    asm("{ .reg .u64 t; cvta.to.shared.u64 t, %1; cvt.u32.u64 %0, t; }" : "=r"(a) : "l"(p));
    return a;
}
__device__ __forceinline__ void ldsm_x4(unsigned &r0, unsigned &r1, unsigned &r2, unsigned &r3, unsigned a) {
    asm volatile("ldmatrix.sync.aligned.m8n8.x4.shared.b16 {%0,%1,%2,%3}, [%4];"
                 : "=r"(r0), "=r"(r1), "=r"(r2), "=r"(r3) : "r"(a));
}
__device__ __forceinline__ void ldsm_x4t(unsigned &r0, unsigned &r1, unsigned &r2, unsigned &r3, unsigned a) {
    asm volatile("ldmatrix.sync.aligned.m8n8.x4.trans.shared.b16 {%0,%1,%2,%3}, [%4];"
                 : "=r"(r0), "=r"(r1), "=r"(r2), "=r"(r3) : "r"(a));
}
__device__ __forceinline__ void mma16816(float* c, unsigned a0, unsigned a1, unsigned a2, unsigned a3,
                                         unsigned b0, unsigned b1) {
    asm volatile("mma.sync.aligned.m16n8k16.row.col.f32.f16.f16.f32 "
                 "{%0,%1,%2,%3}, {%4,%5,%6,%7}, {%8,%9}, {%0,%1,%2,%3};"
                 : "+f"(c[0]), "+f"(c[1]), "+f"(c[2]), "+f"(c[3])
                 : "r"(a0), "r"(a1), "r"(a2), "r"(a3), "r"(b0), "r"(b1));
}

// -- launch 1: E'(fp16), R'(fp32) + dst histogram(int4) + W2->fp16 + lb reset -
__global__ void k_prep(const float* __restrict__ emb, const float* __restrict__ W1l,
                       const float* __restrict__ W1r, const int* __restrict__ dst,
                       const float* __restrict__ W2l, const float* __restrict__ W2r) {
    int b = blockIdx.x, t = threadIdx.x;
    if (b < 128) {
        __shared__ float se[64];
        if (b == 0) for (int i = t; i < SCAN_NB; i += 128) g_lb[i] = 0ULL;
        if (t < 64) se[t] = emb[b * 64 + t];
        __syncthreads();
        const float* W = (t < 64) ? W1l : W1r;
        int c = t & 63;
        float acc = 0.f;
#pragma unroll 8
        for (int k = 0; k < 64; k++) acc += se[k] * __ldg(W + k * 64 + c);
        if (t < 64) g_EpH[b * 64 + c] = __float2half_rn(acc);
        else        g_Rp[b * 64 + c] = acc;
    } else if (b < 128 + HISTB) {
        int base = (b - 128) * 1024 + t * 4;
        if (base < N_EDGES) {
            int4 d = *(const int4*)(dst + base);
            atomicAdd(&g_deg[d.x], 1);
            atomicAdd(&g_deg[d.y], 1);
            atomicAdd(&g_deg[d.z], 1);
            atomicAdd(&g_deg[d.w], 1);
        }
    } else {
        // convert W2 to fp16 concat [W2r; W2l] (8192 values over 4 blocks)
        int idx0 = (b - 128 - HISTB) * 2048 + t * 8;
#pragma unroll
        for (int i = 0; i < 8; i++) {
            int idx = idx0 + i;
            int k = idx >> 6, j = idx & 63;
            float v = (k < 64) ? __ldg(W2r + k * 64 + j) : __ldg(W2l + (k - 64) * 64 + j);
            g_W2h[idx] = __float2half_rn(v);
        }
    }
}

// ---------------- launch 2: single-pass decoupled-lookback scan -------------
__global__ void __launch_bounds__(SCAN_BS) k_scanlb() {
    __shared__ int s[SCAN_BS];
    __shared__ int s_prefix;
    int t = threadIdx.x, bid = blockIdx.x;
    int i = bid * SCAN_BS + t;
    int v = (i < N_NODES) ? g_deg[i] : 0;
    s[t] = v;
    __syncthreads();
    for (int off = 1; off < SCAN_BS; off <<= 1) {
        int x = (t >= off) ? s[t - off] : 0;
        __syncthreads();
        s[t] += x;
        __syncthreads();
    }
    int incl = s[t];
    int total = s[SCAN_BS - 1];
    if (t < 32) {
        unsigned prefix = 0;
        if (bid == 0) {
            if (t == 0) atomicExch(&g_lb[0], (2ULL << 32) | (unsigned)total);
        } else {
            if (t == 0) atomicExch(&g_lb[bid], (1ULL << 32) | (unsigned)total);
            int p = bid - 1;
            while (true) {
                int idx = p - t;
                u64 st = 0;
                if (idx >= 0) {
                    do { st = atomicAdd(&g_lb[idx], 0ULL); } while ((st >> 32) == 0);
                }
                unsigned pm = __ballot_sync(0xffffffffu, idx >= 0 && (st >> 32) == 2);
                unsigned val;
                if (pm) {
                    int closest = __ffs(pm) - 1;
                    val = (t <= closest) ? (unsigned)st : 0u;
                } else {
                    val = (idx >= 0) ? (unsigned)st : 0u;
                }
#pragma unroll
                for (int o = 16; o; o >>= 1) val += __shfl_xor_sync(0xffffffffu, val, o);
                prefix += val;
                if (pm) break;
                p -= 32;
            }
            if (t == 0) atomicExch(&g_lb[bid], (2ULL << 32) | (unsigned)(prefix + (unsigned)total));
        }
        if (t == 0) s_prefix = (int)prefix;
    }
    __syncthreads();
    int excl = incl - v + s_prefix;
    if (i < N_NODES) {
        g_rowptr[i] = excl;
        g_cursor[i] = excl;
        if (i == N_NODES - 1) g_rowptr[N_NODES] = excl + v;
    }
}

// --- launch 3: CSR fill (4 edges/thread) + deg reset + graph-start table ----
__global__ void k_fill(const int* __restrict__ src, const int* __restrict__ dst,
                       const int* __restrict__ x, const int* __restrict__ batch) {
    int tid = blockIdx.x * blockDim.x + threadIdx.x;
    if (tid < N_NODES) {
        g_deg[tid] = 0;
        int b = __ldg(batch + tid);
        int bprev = (tid == 0) ? -1 : __ldg(batch + tid - 1);
        for (int g = bprev + 1; g <= b; g++) g_gstart[g] = tid;
        if (tid == N_NODES - 1)
            for (int g = b + 1; g <= N_GRAPHS; g++) g_gstart[g] = N_NODES;
    }
    int base = tid * 4;
    if (base >= N_EDGES) return;
    int s0 = __ldg(src + base), s1 = __ldg(src + base + 1);
    int s2 = __ldg(src + base + 2), s3 = __ldg(src + base + 3);
    int d0 = __ldg(dst + base), d1 = __ldg(dst + base + 1);
    int d2 = __ldg(dst + base + 2), d3 = __ldg(dst + base + 3);
    int v0 = __ldg(x + s0), v1 = __ldg(x + s1);
    int v2 = __ldg(x + s2), v3 = __ldg(x + s3);
    int p0 = atomicAdd(&g_cursor[d0], 1);
    int p1 = atomicAdd(&g_cursor[d1], 1);
    int p2 = atomicAdd(&g_cursor[d2], 1);
    int p3 = atomicAdd(&g_cursor[d3], 1);
    g_colsrc[p0] = s0; g_colvid[p0] = (u8)v0;
    g_colsrc[p1] = s1; g_colvid[p1] = (u8)v1;
    g_colsrc[p2] = s2; g_colvid[p2] = (u8)v2;
    g_colsrc[p3] = s3; g_colvid[p3] = (u8)v3;
}

// launch 4 [capture slot]: conv1 fused, 2 nodes/warp, byte-vid gather + HADD2
__global__ void k_agg1(const int* __restrict__ x, const float* __restrict__ b1) {
    int w = (blockIdx.x * blockDim.x + threadIdx.x) >> 5;
    int lane = threadIdx.x & 31;
    int n = 2 * w + (lane >> 4);
    if (n >= N_NODES) return;
    int sub = lane & 15;
    int s = g_rowptr[n], e = g_rowptr[n + 1];
    const uint2* ep = (const uint2*)g_EpH;     // row = 16 uint2
    unsigned A0 = 0, B0 = 0, A1 = 0, B1 = 0;
    int i = s;
    int ahead = min(e, (s + 3) & ~3);
    // scalar head to 4-byte alignment
    for (; i < ahead; i++) {
        int r = __ldg(g_colvid + i);
        uint2 v = __ldg(ep + r * 16 + sub);
        hadd2(A0, v.x); hadd2(B0, v.y);
    }
    // aligned main: 4 vids per LDG.32
    for (; i + 4 <= e; i += 4) {
        unsigned w4 = *(const unsigned*)(g_colvid + i);
        int r0 = w4 & 255, r1 = (w4 >> 8) & 255;
        int r2 = (w4 >> 16) & 255, r3 = w4 >> 24;
        uint2 v0 = __ldg(ep + r0 * 16 + sub);
        uint2 v1 = __ldg(ep + r1 * 16 + sub);
        uint2 v2 = __ldg(ep + r2 * 16 + sub);
        uint2 v3 = __ldg(ep + r3 * 16 + sub);
        hadd2(A0, v0.x); hadd2(B0, v0.y);
        hadd2(A1, v1.x); hadd2(B1, v1.y);
        hadd2(A0, v2.x); hadd2(B0, v2.y);
        hadd2(A1, v3.x); hadd2(B1, v3.y);
    }
    // scalar tail
    for (; i < e; i++) {
        int r = __ldg(g_colvid + i);
        uint2 v = __ldg(ep + r * 16 + sub);
        hadd2(A0, v.x); hadd2(B0, v.y);
    }
    hadd2(A0, A1); hadd2(B0, B1);
    int cnt = e - s;
    float inv = __fdividef(1.f, (float)max(cnt, 1));
    float2 p = h2f(A0), q = h2f(B0);
    int vid = __ldg(x + n);
    float4 r = *(const float4*)(g_Rp + vid * 64 + sub * 4);
    float4 bb = *(const float4*)(b1 + sub * 4);
    float o0 = fmaxf(fmaf(p.x, inv, r.x + bb.x), 0.f);
    float o1 = fmaxf(fmaf(p.y, inv, r.y + bb.y), 0.f);
    float o2 = fmaxf(fmaf(q.x, inv, r.z + bb.z), 0.f);
    float o3 = fmaxf(fmaf(q.y, inv, r.w + bb.w), 0.f);
    __half2 h0 = __floats2half2_rn(o0, o1);
    __half2 h1 = __floats2half2_rn(o2, o3);
    uint2 st; st.x = *(unsigned*)&h0; st.y = *(unsigned*)&h1;
    *((uint2*)g_hBh + n * 16 + sub) = st;
}

// launch 5: conv2 aggregation — 2 nodes/warp, int4 index loads + HADD2
__global__ void k_agg() {
    int w = (blockIdx.x * blockDim.x + threadIdx.x) >> 5;
    int lane = threadIdx.x & 31;
    int n = 2 * w + (lane >> 4);
    if (n >= N_NODES) return;
    int sub = lane & 15;
    int s = g_rowptr[n], e = g_rowptr[n + 1];
    const uint2* hb = (const uint2*)g_hBh;
    unsigned A0 = 0, B0 = 0, A1 = 0, B1 = 0;
    int i = s;
    int ahead = min(e, (s + 3) & ~3);
    for (; i < ahead; i++) {
        int u = __ldg(g_colsrc + i);
        uint2 v = __ldg(hb + u * 16 + sub);
        hadd2(A0, v.x); hadd2(B0, v.y);
    }
    for (; i + 4 <= e; i += 4) {
        int4 u = *(const int4*)(g_colsrc + i);
        uint2 v0 = __ldg(hb + u.x * 16 + sub);
        uint2 v1 = __ldg(hb + u.y * 16 + sub);
        uint2 v2 = __ldg(hb + u.z * 16 + sub);
        uint2 v3 = __ldg(hb + u.w * 16 + sub);
        hadd2(A0, v0.x); hadd2(B0, v0.y);
        hadd2(A1, v1.x); hadd2(B1, v1.y);
        hadd2(A0, v2.x); hadd2(B0, v2.y);
        hadd2(A1, v3.x); hadd2(B1, v3.y);
    }
    for (; i < e; i++) {
        int u = __ldg(g_colsrc + i);
        uint2 v = __ldg(hb + u * 16 + sub);
        hadd2(A0, v.x); hadd2(B0, v.y);
    }
    hadd2(A0, A1); hadd2(B0, B1);
    int cnt = e - s;
    float inv = __fdividef(1.f, (float)max(cnt, 1));
    float2 p = h2f(A0), q = h2f(B0);
    __half2 h0 = __floats2half2_rn(p.x * inv, p.y * inv);
    __half2 h1 = __floats2half2_rn(q.x * inv, q.y * inv);
    uint2 st; st.x = *(unsigned*)&h0; st.y = *(unsigned*)&h1;
    *((uint2*)g_meanH + n * 16 + sub) = st;
}

// launch 6: conv2 dual GEMM via HMMA tensor cores + bias + relu --------------
__global__ void __launch_bounds__(256)
k_mmtc(const float* __restrict__ bias, float* __restrict__ out) {
    extern __shared__ __half sm[];
    __half* sA = sm;                    // 128 x SA_H
    __half* sB = sm + 128 * SA_H;       // 128 x SB_H
    int t = threadIdx.x;
    int nbase = blockIdx.x * 128;
#pragma unroll
    for (int it = 0; it < 4; it++) {
        int idx = it * 256 + t;
        int row = idx >> 3, ch = idx & 7;
        uint4 v = *((const uint4*)(g_W2h + row * 64) + ch);
        *(uint4*)(sB + row * SB_H + ch * 8) = v;
    }
#pragma unroll
    for (int it = 0; it < 8; it++) {
        int idx = it * 256 + t;
        int row = idx >> 4, ch = idx & 15;
        uint4 v = (ch < 8)
            ? *((const uint4*)(g_hBh + (nbase + row) * 64) + ch)
            : *((const uint4*)(g_meanH + (nbase + row) * 64) + (ch - 8));
        *(uint4*)(sA + row * SA_H + ch * 8) = v;
    }
    __syncthreads();

    int w = t >> 5, lane = t & 31;
    unsigned aBase = smem_u32(sA) + ((w * 16 + (lane & 15)) * SA_H + (lane >> 4) * 8) * 2;
    unsigned bBase = smem_u32(sB) + ((lane & 15) * SB_H) * 2 + (lane >> 4) * 16;

    float c[8][4];
#pragma unroll
    for (int nt = 0; nt < 8; nt++) {
        float x0 = __ldg(bias + nt * 8 + (lane & 3) * 2);
        float x1 = __ldg(bias + nt * 8 + (lane & 3) * 2 + 1);
        c[nt][0] = x0; c[nt][1] = x1; c[nt][2] = x0; c[nt][3] = x1;
    }
#pragma unroll
    for (int kc = 0; kc < 8; kc++) {
        unsigned a0, a1, a2, a3;
        ldsm_x4(a0, a1, a2, a3, aBase + kc * 32);
#pragma unroll
        for (int j = 0; j < 4; j++) {
            unsigned b0, b1, b2, b3;
            ldsm_x4t(b0, b1, b2, b3, bBase + kc * 16 * SB_H * 2 + j * 32);
            mma16816(c[2 * j],     a0, a1, a2, a3, b0, b1);
            mma16816(c[2 * j + 1], a0, a1, a2, a3, b2, b3);
        }
    }
    int r0 = nbase + w * 16 + (lane >> 2);
    int r1 = r0 + 8;
    int cb = (lane & 3) * 2;
    bool v0 = r0 < N_NODES, v1 = r1 < N_NODES;
#pragma unroll
    for (int nt = 0; nt < 8; nt++) {
        if (v0) {
            float2 o; o.x = fmaxf(c[nt][0], 0.f); o.y = fmaxf(c[nt][1], 0.f);
            *(float2*)(out + r0 * 64 + nt * 8 + cb) = o;
        }
        if (v1) {
            float2 o; o.x = fmaxf(c[nt][2], 0.f); o.y = fmaxf(c[nt][3], 0.f);
            *(float2*)(out + r1 * 64 + nt * 8 + cb) = o;
        }
    }
}

// ---- launch 7: mean-pool + output head (warp per graph, gstart table) ------
__global__ void k_pool(const float* __restrict__ h,
                       const float* __restrict__ Wout, const float* __restrict__ bout,
                       float* __restrict__ out) {
    int g = (blockIdx.x * blockDim.x + threadIdx.x) >> 5;
    if (g >= N_GRAPHS) return;
    int lane = threadIdx.x & 31;
    int s = g_gstart[g], e = g_gstart[g + 1];
    float a0 = 0.f, a1 = 0.f, b0 = 0.f, b1 = 0.f;
    int n = s;
    for (; n + 2 <= e; n += 2) {
        a0 += __ldg(h + n * 64 + lane);
        a1 += __ldg(h + n * 64 + lane + 32);
        b0 += __ldg(h + (n + 1) * 64 + lane);
        b1 += __ldg(h + (n + 1) * 64 + lane + 32);
    }
    if (n < e) {
        a0 += __ldg(h + n * 64 + lane);
        a1 += __ldg(h + n * 64 + lane + 32);
    }
    a0 += b0; a1 += b1;
    float inv = __fdividef(1.f, (float)max(e - s, 1));
    a0 *= inv; a1 *= inv;
    float p0 = a0 * __ldg(Wout + lane * 2 + 0) + a1 * __ldg(Wout + (lane + 32) * 2 + 0);
    float p1 = a0 * __ldg(Wout + lane * 2 + 1) + a1 * __ldg(Wout + (lane + 32) * 2 + 1);
#pragma unroll
    for (int off = 16; off; off >>= 1) {
        p0 += __shfl_xor_sync(0xffffffffu, p0, off);
        p1 += __shfl_xor_sync(0xffffffffu, p1, off);
    }
    if (lane == 0) {
        out[g * 2 + 0] = p0 + __ldg(bout + 0);
        out[g * 2 + 1] = p1 + __ldg(bout + 1);
    }
}

// ---------------- launch ----------------
extern "C" void kernel_launch(void* const* d_in, const int* in_sizes, int n_in,
                              void* d_out, int out_size) {
    const int*   x     = (const int*)d_in[0];
    const int*   ei    = (const int*)d_in[1];
    const int*   batch = (const int*)d_in[2];
    const float* emb   = (const float*)d_in[3];
    const float* W1l   = (const float*)d_in[4];
    const float* b1    = (const float*)d_in[5];
    const float* W1r   = (const float*)d_in[6];
    const float* W2l   = (const float*)d_in[7];
    const float* b2    = (const float*)d_in[8];
    const float* W2r   = (const float*)d_in[9];
    const float* Wo    = (const float*)d_in[10];
    const float* bo    = (const float*)d_in[11];
    const int* src = ei;
    const int* dst = ei + N_EDGES;
    float* out = (float*)d_out;

    float* hA;
    cudaGetSymbolAddress((void**)&hA, g_hA);

    static bool attr_done = false;
    if (!attr_done) {
        cudaFuncSetAttribute(k_mmtc, cudaFuncAttributeMaxDynamicSharedMemorySize, SMEM_MM);
        attr_done = true;
    }

    const int aggBlocks = ((N_NODES + 1) / 2 * 32 + 255) / 256;   // 2 nodes/warp

    // 1: weight transforms + dst histogram + lb reset
    k_prep<<<128 + HISTB + 4, 256>>>(emb, W1l, W1r, dst, W2l, W2r);
    // 2: rowptr/cursor via lookback scan
    k_scanlb<<<SCAN_NB, SCAN_BS>>>();
    // 3: CSR fill (4 edges/thread, split id/vid arrays) + deg reset + gstart
    k_fill<<<(N_EDGES / 4 + 255) / 256, 256>>>(src, dst, x, batch);

    // 4: conv1 fused (byte-vid gather + HADD2)   <-- ncu capture slot
    k_agg1<<<aggBlocks, 256>>>(x, b1);

    // 5: conv2 aggregation -> fp16 mean (int4 index loads)
    k_agg<<<aggBlocks, 256>>>();
    // 6: conv2 dual GEMM on tensor cores
    k_mmtc<<<(N_NODES + 127) / 128, 256, SMEM_MM>>>(b2, hA);

    // 7: pool + head (gstart table)
    k_pool<<<(N_GRAPHS * 32 + 255) / 256, 256>>>(hA, Wo, bo, out);
}

// round 16
// speedup vs baseline: 1.0859x; 1.0859x over previous
#include <cuda_runtime.h>
#include <cuda_fp16.h>

#define N_NODES 100000
#define N_EDGES 1000000
#define N_GRAPHS 2048
#define SCAN_BS 512
#define SCAN_NB ((N_NODES + SCAN_BS - 1) / SCAN_BS)
#define HISTB ((N_EDGES + 1023) / 1024)
#define PADN (N_NODES + 128)
// k_mmtc smem: A tile 128 x 136 halves, B tile 128 x 72 halves
#define SA_H 136
#define SB_H 72
#define SMEM_MM (128 * SA_H * 2 + 128 * SB_H * 2)

typedef unsigned long long u64;

// ---------------- device scratch (no allocs allowed) ----------------
__device__ float  g_hA[N_NODES * 64];
__device__ __half g_hBh[PADN * 64];       // conv1 output, fp16 (padded rows)
__device__ __half g_meanH[PADN * 64];     // conv2 mean, fp16 (padded rows)
__device__ __half g_EpH[128 * 64];        // emb @ W1l, fp16 (16 KB, L1-resident)
__device__ float  g_Rp[128 * 64];         // emb @ W1r, fp32
__device__ __half g_W2h[128 * 64];        // rows 0-63 = W2r, 64-127 = W2l (fp16)
__device__ int    g_deg[N_NODES];         // INVARIANT: zero at kernel_launch entry
__device__ int    g_rowptr[N_NODES + 1];
__device__ int    g_cursor[N_NODES];
__device__ int    g_colsrc[N_EDGES];      // packed: src_node | (vocab_id << 20)
__device__ int    g_gstart[N_GRAPHS + 1]; // graph -> first node index (batch sorted)
__device__ u64    g_lb[SCAN_NB];

// ---------------- helpers ----------------
__device__ __forceinline__ void hadd2(unsigned &d, unsigned a) {
    asm("add.rn.f16x2 %0, %0, %1;" : "+r"(d) : "r"(a));
}
__device__ __forceinline__ float2 h2f(unsigned h) {
    __half2 v = *reinterpret_cast<__half2*>(&h);
    return __half22float2(v);
}
__device__ __forceinline__ unsigned smem_u32(const void* p) {
    unsigned a;
    asm("{ .reg .u64 t; cvta.to.shared.u64 t, %1; cvt.u32.u64 %0, t; }" : "=r"(a) : "l"(p));
    return a;
}
__device__ __forceinline__ void ldsm_x4(unsigned &r0, unsigned &r1, unsigned &r2, unsigned &r3, unsigned a) {
    asm volatile("ldmatrix.sync.aligned.m8n8.x4.shared.b16 {%0,%1,%2,%3}, [%4];"
                 : "=r"(r0), "=r"(r1), "=r"(r2), "=r"(r3) : "r"(a));
}
__device__ __forceinline__ void ldsm_x4t(unsigned &r0, unsigned &r1, unsigned &r2, unsigned &r3, unsigned a) {
    asm volatile("ldmatrix.sync.aligned.m8n8.x4.trans.shared.b16 {%0,%1,%2,%3}, [%4];"
                 : "=r"(r0), "=r"(r1), "=r"(r2), "=r"(r3) : "r"(a));
}
__device__ __forceinline__ void mma16816(float* c, unsigned a0, unsigned a1, unsigned a2, unsigned a3,
                                         unsigned b0, unsigned b1) {
    asm volatile("mma.sync.aligned.m16n8k16.row.col.f32.f16.f16.f32 "
                 "{%0,%1,%2,%3}, {%4,%5,%6,%7}, {%8,%9}, {%0,%1,%2,%3};"
                 : "+f"(c[0]), "+f"(c[1]), "+f"(c[2]), "+f"(c[3])
                 : "r"(a0), "r"(a1), "r"(a2), "r"(a3), "r"(b0), "r"(b1));
}

// -- launch 1: E'(fp16), R'(fp32) + dst histogram(int4) + W2->fp16 + lb reset -
__global__ void k_prep(const float* __restrict__ emb, const float* __restrict__ W1l,
                       const float* __restrict__ W1r, const int* __restrict__ dst,
                       const float* __restrict__ W2l, const float* __restrict__ W2r) {
    int b = blockIdx.x, t = threadIdx.x;
    if (b < 128) {
        __shared__ float se[64];
        if (b == 0) for (int i = t; i < SCAN_NB; i += 128) g_lb[i] = 0ULL;
        if (t < 64) se[t] = emb[b * 64 + t];
        __syncthreads();
        const float* W = (t < 64) ? W1l : W1r;
        int c = t & 63;
        float acc = 0.f;
#pragma unroll 8
        for (int k = 0; k < 64; k++) acc += se[k] * __ldg(W + k * 64 + c);
        if (t < 64) g_EpH[b * 64 + c] = __float2half_rn(acc);
        else        g_Rp[b * 64 + c] = acc;
    } else if (b < 128 + HISTB) {
        int base = (b - 128) * 1024 + t * 4;
        if (base < N_EDGES) {
            int4 d = *(const int4*)(dst + base);
            atomicAdd(&g_deg[d.x], 1);
            atomicAdd(&g_deg[d.y], 1);
            atomicAdd(&g_deg[d.z], 1);
            atomicAdd(&g_deg[d.w], 1);
        }
    } else {
        // convert W2 to fp16 concat [W2r; W2l] (8192 values over 4 blocks)
        int idx0 = (b - 128 - HISTB) * 2048 + t * 8;
#pragma unroll
        for (int i = 0; i < 8; i++) {
            int idx = idx0 + i;
            int k = idx >> 6, j = idx & 63;
            float v = (k < 64) ? __ldg(W2r + k * 64 + j) : __ldg(W2l + (k - 64) * 64 + j);
            g_W2h[idx] = __float2half_rn(v);
        }
    }
}

// ---------------- launch 2: single-pass decoupled-lookback scan -------------
__global__ void __launch_bounds__(SCAN_BS) k_scanlb() {
    __shared__ int s[SCAN_BS];
    __shared__ int s_prefix;
    int t = threadIdx.x, bid = blockIdx.x;
    int i = bid * SCAN_BS + t;
    int v = (i < N_NODES) ? g_deg[i] : 0;
    s[t] = v;
    __syncthreads();
    for (int off = 1; off < SCAN_BS; off <<= 1) {
        int x = (t >= off) ? s[t - off] : 0;
        __syncthreads();
        s[t] += x;
        __syncthreads();
    }
    int incl = s[t];
    int total = s[SCAN_BS - 1];
    if (t < 32) {
        unsigned prefix = 0;
        if (bid == 0) {
            if (t == 0) atomicExch(&g_lb[0], (2ULL << 32) | (unsigned)total);
        } else {
            if (t == 0) atomicExch(&g_lb[bid], (1ULL << 32) | (unsigned)total);
            int p = bid - 1;
            while (true) {
                int idx = p - t;
                u64 st = 0;
                if (idx >= 0) {
                    do { st = atomicAdd(&g_lb[idx], 0ULL); } while ((st >> 32) == 0);
                }
                unsigned pm = __ballot_sync(0xffffffffu, idx >= 0 && (st >> 32) == 2);
                unsigned val;
                if (pm) {
                    int closest = __ffs(pm) - 1;
                    val = (t <= closest) ? (unsigned)st : 0u;
                } else {
                    val = (idx >= 0) ? (unsigned)st : 0u;
                }
#pragma unroll
                for (int o = 16; o; o >>= 1) val += __shfl_xor_sync(0xffffffffu, val, o);
                prefix += val;
                if (pm) break;
                p -= 32;
            }
            if (t == 0) atomicExch(&g_lb[bid], (2ULL << 32) | (unsigned)(prefix + (unsigned)total));
        }
        if (t == 0) s_prefix = (int)prefix;
    }
    __syncthreads();
    int excl = incl - v + s_prefix;
    if (i < N_NODES) {
        g_rowptr[i] = excl;
        g_cursor[i] = excl;
        if (i == N_NODES - 1) g_rowptr[N_NODES] = excl + v;
    }
}

// --- launch 3: CSR fill (4 edges/thread, int4 loads) + deg reset + gstart ---
__global__ void k_fill(const int* __restrict__ src, const int* __restrict__ dst,
                       const int* __restrict__ x, const int* __restrict__ batch) {
    int tid = blockIdx.x * blockDim.x + threadIdx.x;
    if (tid < N_NODES) {
        g_deg[tid] = 0;
        int b = __ldg(batch + tid);
        int bprev = (tid == 0) ? -1 : __ldg(batch + tid - 1);
        for (int g = bprev + 1; g <= b; g++) g_gstart[g] = tid;
        if (tid == N_NODES - 1)
            for (int g = b + 1; g <= N_GRAPHS; g++) g_gstart[g] = N_NODES;
    }
    int base = tid * 4;
    if (base >= N_EDGES) return;
    int4 sv = *(const int4*)(src + base);
    int4 dv = *(const int4*)(dst + base);
    int v0 = __ldg(x + sv.x), v1 = __ldg(x + sv.y);
    int v2 = __ldg(x + sv.z), v3 = __ldg(x + sv.w);
    int p0 = atomicAdd(&g_cursor[dv.x], 1);
    int p1 = atomicAdd(&g_cursor[dv.y], 1);
    int p2 = atomicAdd(&g_cursor[dv.z], 1);
    int p3 = atomicAdd(&g_cursor[dv.w], 1);
    g_colsrc[p0] = sv.x | (v0 << 20);
    g_colsrc[p1] = sv.y | (v1 << 20);
    g_colsrc[p2] = sv.z | (v2 << 20);
    g_colsrc[p3] = sv.w | (v3 << 20);
}

// launch 4 [capture slot]: conv1 fused, 2 nodes/warp, fp16 gather + HADD2, x4 unroll
__global__ void k_agg1(const int* __restrict__ x, const float* __restrict__ b1) {
    int w = (blockIdx.x * blockDim.x + threadIdx.x) >> 5;
    int lane = threadIdx.x & 31;
    int n = 2 * w + (lane >> 4);
    if (n >= N_NODES) return;
    int sub = lane & 15;
    int s = g_rowptr[n], e = g_rowptr[n + 1];
    int cnt = e - s;
    const uint2* ep = (const uint2*)g_EpH;
    unsigned A0 = 0, B0 = 0, A1 = 0, B1 = 0;
    int i = 0;
    for (; i + 4 <= cnt; i += 4) {
        int u0 = __ldg(g_colsrc + s + i);
        int u1 = __ldg(g_colsrc + s + i + 1);
        int u2 = __ldg(g_colsrc + s + i + 2);
        int u3 = __ldg(g_colsrc + s + i + 3);
        uint2 v0 = __ldg(ep + (u0 >> 20) * 16 + sub);
        uint2 v1 = __ldg(ep + (u1 >> 20) * 16 + sub);
        uint2 v2 = __ldg(ep + (u2 >> 20) * 16 + sub);
        uint2 v3 = __ldg(ep + (u3 >> 20) * 16 + sub);
        hadd2(A0, v0.x); hadd2(B0, v0.y);
        hadd2(A1, v1.x); hadd2(B1, v1.y);
        hadd2(A0, v2.x); hadd2(B0, v2.y);
        hadd2(A1, v3.x); hadd2(B1, v3.y);
    }
    if (i + 2 <= cnt) {
        int u0 = __ldg(g_colsrc + s + i);
        int u1 = __ldg(g_colsrc + s + i + 1);
        uint2 v0 = __ldg(ep + (u0 >> 20) * 16 + sub);
        uint2 v1 = __ldg(ep + (u1 >> 20) * 16 + sub);
        hadd2(A0, v0.x); hadd2(B0, v0.y);
        hadd2(A1, v1.x); hadd2(B1, v1.y);
        i += 2;
    }
    if (i < cnt) {
        int u = __ldg(g_colsrc + s + i);
        uint2 v = __ldg(ep + (u >> 20) * 16 + sub);
        hadd2(A0, v.x); hadd2(B0, v.y);
    }
    hadd2(A0, A1); hadd2(B0, B1);
    float inv = __fdividef(1.f, (float)max(cnt, 1));
    float2 p = h2f(A0), q = h2f(B0);
    int vid = __ldg(x + n);
    float4 r = *(const float4*)(g_Rp + vid * 64 + sub * 4);
    float4 bb = *(const float4*)(b1 + sub * 4);
    float o0 = fmaxf(fmaf(p.x, inv, r.x + bb.x), 0.f);
    float o1 = fmaxf(fmaf(p.y, inv, r.y + bb.y), 0.f);
    float o2 = fmaxf(fmaf(q.x, inv, r.z + bb.z), 0.f);
    float o3 = fmaxf(fmaf(q.y, inv, r.w + bb.w), 0.f);
    __half2 h0 = __floats2half2_rn(o0, o1);
    __half2 h1 = __floats2half2_rn(o2, o3);
    uint2 st; st.x = *(unsigned*)&h0; st.y = *(unsigned*)&h1;
    *((uint2*)g_hBh + n * 16 + sub) = st;
}

// launch 5: conv2 aggregation — 2 nodes/warp, fp16 gather + HADD2, x4 unroll
__global__ void k_agg() {
    int w = (blockIdx.x * blockDim.x + threadIdx.x) >> 5;
    int lane = threadIdx.x & 31;
    int n = 2 * w + (lane >> 4);
    if (n >= N_NODES) return;
    int sub = lane & 15;
    int s = g_rowptr[n], e = g_rowptr[n + 1];
    int cnt = e - s;
    const uint2* hb = (const uint2*)g_hBh;
    unsigned A0 = 0, B0 = 0, A1 = 0, B1 = 0;
    int i = 0;
    for (; i + 4 <= cnt; i += 4) {
        int u0 = __ldg(g_colsrc + s + i);
        int u1 = __ldg(g_colsrc + s + i + 1);
        int u2 = __ldg(g_colsrc + s + i + 2);
        int u3 = __ldg(g_colsrc + s + i + 3);
        uint2 v0 = __ldg(hb + (u0 & 0xFFFFF) * 16 + sub);
        uint2 v1 = __ldg(hb + (u1 & 0xFFFFF) * 16 + sub);
        uint2 v2 = __ldg(hb + (u2 & 0xFFFFF) * 16 + sub);
        uint2 v3 = __ldg(hb + (u3 & 0xFFFFF) * 16 + sub);
        hadd2(A0, v0.x); hadd2(B0, v0.y);
        hadd2(A1, v1.x); hadd2(B1, v1.y);
        hadd2(A0, v2.x); hadd2(B0, v2.y);
        hadd2(A1, v3.x); hadd2(B1, v3.y);
    }
    if (i + 2 <= cnt) {
        int u0 = __ldg(g_colsrc + s + i);
        int u1 = __ldg(g_colsrc + s + i + 1);
        uint2 v0 = __ldg(hb + (u0 & 0xFFFFF) * 16 + sub);
        uint2 v1 = __ldg(hb + (u1 & 0xFFFFF) * 16 + sub);
        hadd2(A0, v0.x); hadd2(B0, v0.y);
        hadd2(A1, v1.x); hadd2(B1, v1.y);
        i += 2;
    }
    if (i < cnt) {
        int u = __ldg(g_colsrc + s + i);
        uint2 v = __ldg(hb + (u & 0xFFFFF) * 16 + sub);
        hadd2(A0, v.x); hadd2(B0, v.y);
    }
    hadd2(A0, A1); hadd2(B0, B1);
    float inv = __fdividef(1.f, (float)max(cnt, 1));
    float2 p = h2f(A0), q = h2f(B0);
    __half2 h0 = __floats2half2_rn(p.x * inv, p.y * inv);
    __half2 h1 = __floats2half2_rn(q.x * inv, q.y * inv);
    uint2 st; st.x = *(unsigned*)&h0; st.y = *(unsigned*)&h1;
    *((uint2*)g_meanH + n * 16 + sub) = st;
}

// launch 6: conv2 dual GEMM via HMMA tensor cores + bias + relu --------------
__global__ void __launch_bounds__(256)
k_mmtc(const float* __restrict__ bias, float* __restrict__ out) {
    extern __shared__ __half sm[];
    __half* sA = sm;                    // 128 x SA_H
    __half* sB = sm + 128 * SA_H;       // 128 x SB_H
    int t = threadIdx.x;
    int nbase = blockIdx.x * 128;
#pragma unroll
    for (int it = 0; it < 4; it++) {
        int idx = it * 256 + t;
        int row = idx >> 3, ch = idx & 7;
        uint4 v = *((const uint4*)(g_W2h + row * 64) + ch);
        *(uint4*)(sB + row * SB_H + ch * 8) = v;
    }
#pragma unroll
    for (int it = 0; it < 8; it++) {
        int idx = it * 256 + t;
        int row = idx >> 4, ch = idx & 15;
        uint4 v = (ch < 8)
            ? *((const uint4*)(g_hBh + (nbase + row) * 64) + ch)
            : *((const uint4*)(g_meanH + (nbase + row) * 64) + (ch - 8));
        *(uint4*)(sA + row * SA_H + ch * 8) = v;
    }
    __syncthreads();

    int w = t >> 5, lane = t & 31;
    unsigned aBase = smem_u32(sA) + ((w * 16 + (lane & 15)) * SA_H + (lane >> 4) * 8) * 2;
    unsigned bBase = smem_u32(sB) + ((lane & 15) * SB_H) * 2 + (lane >> 4) * 16;

    float c[8][4];
#pragma unroll
    for (int nt = 0; nt < 8; nt++) {
        float x0 = __ldg(bias + nt * 8 + (lane & 3) * 2);
        float x1 = __ldg(bias + nt * 8 + (lane & 3) * 2 + 1);
        c[nt][0] = x0; c[nt][1] = x1; c[nt][2] = x0; c[nt][3] = x1;
    }
#pragma unroll
    for (int kc = 0; kc < 8; kc++) {
        unsigned a0, a1, a2, a3;
        ldsm_x4(a0, a1, a2, a3, aBase + kc * 32);
#pragma unroll
        for (int j = 0; j < 4; j++) {
            unsigned b0, b1, b2, b3;
            ldsm_x4t(b0, b1, b2, b3, bBase + kc * 16 * SB_H * 2 + j * 32);
            mma16816(c[2 * j],     a0, a1, a2, a3, b0, b1);
            mma16816(c[2 * j + 1], a0, a1, a2, a3, b2, b3);
        }
    }
    int r0 = nbase + w * 16 + (lane >> 2);
    int r1 = r0 + 8;
    int cb = (lane & 3) * 2;
    bool v0 = r0 < N_NODES, v1 = r1 < N_NODES;
#pragma unroll
    for (int nt = 0; nt < 8; nt++) {
        if (v0) {
            float2 o; o.x = fmaxf(c[nt][0], 0.f); o.y = fmaxf(c[nt][1], 0.f);
            *(float2*)(out + r0 * 64 + nt * 8 + cb) = o;
        }
        if (v1) {
            float2 o; o.x = fmaxf(c[nt][2], 0.f); o.y = fmaxf(c[nt][3], 0.f);
            *(float2*)(out + r1 * 64 + nt * 8 + cb) = o;
        }
    }
}

// ---- launch 7: mean-pool + output head (warp per graph, gstart table) ------
__global__ void k_pool(const float* __restrict__ h,
                       const float* __restrict__ Wout, const float* __restrict__ bout,
                       float* __restrict__ out) {
    int g = (blockIdx.x * blockDim.x + threadIdx.x) >> 5;
    if (g >= N_GRAPHS) return;
    int lane = threadIdx.x & 31;
    int s = g_gstart[g], e = g_gstart[g + 1];
    float a0 = 0.f, a1 = 0.f, b0 = 0.f, b1 = 0.f;
    int n = s;
    for (; n + 2 <= e; n += 2) {
        a0 += __ldg(h + n * 64 + lane);
        a1 += __ldg(h + n * 64 + lane + 32);
        b0 += __ldg(h + (n + 1) * 64 + lane);
        b1 += __ldg(h + (n + 1) * 64 + lane + 32);
    }
    if (n < e) {
        a0 += __ldg(h + n * 64 + lane);
        a1 += __ldg(h + n * 64 + lane + 32);
    }
    a0 += b0; a1 += b1;
    float inv = __fdividef(1.f, (float)max(e - s, 1));
    a0 *= inv; a1 *= inv;
    float p0 = a0 * __ldg(Wout + lane * 2 + 0) + a1 * __ldg(Wout + (lane + 32) * 2 + 0);
    float p1 = a0 * __ldg(Wout + lane * 2 + 1) + a1 * __ldg(Wout + (lane + 32) * 2 + 1);
#pragma unroll
    for (int off = 16; off; off >>= 1) {
        p0 += __shfl_xor_sync(0xffffffffu, p0, off);
        p1 += __shfl_xor_sync(0xffffffffu, p1, off);
    }
    if (lane == 0) {
        out[g * 2 + 0] = p0 + __ldg(bout + 0);
        out[g * 2 + 1] = p1 + __ldg(bout + 1);
    }
}

// ---------------- launch ----------------
extern "C" void kernel_launch(void* const* d_in, const int* in_sizes, int n_in,
                              void* d_out, int out_size) {
    const int*   x     = (const int*)d_in[0];
    const int*   ei    = (const int*)d_in[1];
    const int*   batch = (const int*)d_in[2];
    const float* emb   = (const float*)d_in[3];
    const float* W1l   = (const float*)d_in[4];
    const float* b1    = (const float*)d_in[5];
    const float* W1r   = (const float*)d_in[6];
    const float* W2l   = (const float*)d_in[7];
    const float* b2    = (const float*)d_in[8];
    const float* W2r   = (const float*)d_in[9];
    const float* Wo    = (const float*)d_in[10];
    const float* bo    = (const float*)d_in[11];
    const int* src = ei;
    const int* dst = ei + N_EDGES;
    float* out = (float*)d_out;

    float* hA;
    cudaGetSymbolAddress((void**)&hA, g_hA);

    static bool attr_done = false;
    if (!attr_done) {
        cudaFuncSetAttribute(k_mmtc, cudaFuncAttributeMaxDynamicSharedMemorySize, SMEM_MM);
        attr_done = true;
    }

    const int aggBlocks = ((N_NODES + 1) / 2 * 32 + 255) / 256;   // 2 nodes/warp

    // 1: weight transforms + dst histogram + lb reset
    k_prep<<<128 + HISTB + 4, 256>>>(emb, W1l, W1r, dst, W2l, W2r);
    // 2: rowptr/cursor via lookback scan
    k_scanlb<<<SCAN_NB, SCAN_BS>>>();
    // 3: CSR fill (4 edges/thread, int4 loads) + deg reset + gstart
    k_fill<<<(N_EDGES / 4 + 255) / 256, 256>>>(src, dst, x, batch);

    // 4: conv1 fused (fp16 gather + HADD2)   <-- ncu capture slot
    k_agg1<<<aggBlocks, 256>>>(x, b1);

    // 5: conv2 aggregation -> fp16 mean (2 nodes/warp)
    k_agg<<<aggBlocks, 256>>>();
    // 6: conv2 dual GEMM on tensor cores
    k_mmtc<<<(N_NODES + 127) / 128, 256, SMEM_MM>>>(b2, hA);

    // 7: pool + head (gstart table)
    k_pool<<<(N_GRAPHS * 32 + 255) / 256, 256>>>(hA, Wo, bo, out);
}